// round 1
// baseline (speedup 1.0000x reference)
#include <cuda_runtime.h>
#include <math.h>

// Problem constants
#define D      256
#define NH     8
#define HD     32
#define NE     5
#define LQ     100
#define LK     1024
#define BB     16
#define MQ     (LQ*BB)      // 1600 query tokens
#define MK     (LK*BB)      // 16384 kv tokens
#define NEXP   (NE*D)       // 1280

// ---------------- scratch (device globals; no allocation allowed) ----------
__device__ float g_qemb[MQ*D];          // tgt + query_pos
__device__ float g_kemb[MK*D];          // memory + pos
__device__ float g_Q[MQ*NEXP];          // (m, e*256+o)
__device__ float g_K[MK*NEXP];
__device__ float g_V[MK*NEXP];
__device__ float g_gate[MQ*NE];
__device__ float g_ctx[NE*MQ*D];        // (e, m, d)
__device__ float g_out[NE*MQ*D];        // (e, m, d)

// ---------------- elementwise add ------------------------------------------
__global__ void addvec_kernel(const float* __restrict__ a,
                              const float* __restrict__ b,
                              float* __restrict__ c, int n4) {
    int i = blockIdx.x * blockDim.x + threadIdx.x;
    if (i < n4) {
        float4 x = ((const float4*)a)[i];
        float4 y = ((const float4*)b)[i];
        float4 z = make_float4(x.x+y.x, x.y+y.y, x.z+y.z, x.w+y.w);
        ((float4*)c)[i] = z;
    }
}

// ---------------- gate: softmax over 5 experts per token -------------------
__global__ void gate_kernel(const float* __restrict__ tgt,
                            const float* __restrict__ wg,
                            const float* __restrict__ bg) {
    int warp = (blockIdx.x * blockDim.x + threadIdx.x) >> 5;
    int lane = threadIdx.x & 31;
    if (warp >= MQ) return;
    const float* x = tgt + warp * D;
    float logit[NE];
    #pragma unroll
    for (int e = 0; e < NE; e++) {
        float s = 0.f;
        #pragma unroll
        for (int k = lane; k < D; k += 32) s = fmaf(x[k], wg[e*D + k], s);
        #pragma unroll
        for (int o = 16; o > 0; o >>= 1) s += __shfl_xor_sync(0xffffffffu, s, o);
        logit[e] = s + bg[e];
    }
    if (lane == 0) {
        float mx = logit[0];
        #pragma unroll
        for (int e = 1; e < NE; e++) mx = fmaxf(mx, logit[e]);
        float p[NE], sum = 0.f;
        #pragma unroll
        for (int e = 0; e < NE; e++) { p[e] = __expf(logit[e] - mx); sum += p[e]; }
        float inv = 1.f / sum;
        #pragma unroll
        for (int e = 0; e < NE; e++) g_gate[warp*NE + e] = p[e] * inv;
    }
}

// ---------------- fp32 SGEMM: C(MxN) = A(Mx256) @ W^T + bias ---------------
// Tiles: 128(M) x 64(N), BK=16, 256 threads, 8x4 per-thread.
// W rows are (o,k) K-major weight rows. Per n-tile (64 cols, within one
// expert since 64|256): Wblk = W + z*wZ + e*wES + wSO + o0*256.
__global__ __launch_bounds__(256)
void sgemm256(const float* __restrict__ A, const float* __restrict__ W,
              const float* __restrict__ bias, float* __restrict__ C,
              int M, int ldc,
              int aZ, int wZ, int bZ, int cZ,
              int wES, int wSO, int bES, int bSO) {
    __shared__ float As[16][132];
    __shared__ float Bs[16][68];

    int z = blockIdx.z;
    A += (long)z * aZ;
    C += (long)z * cZ;
    int n0 = blockIdx.y * 64;
    int e  = n0 >> 8, o0 = n0 & 255;
    const float* Wblk    = W    + (long)z * wZ + (long)e * wES + wSO + o0 * 256;
    const float* biasBlk = bias + (long)z * bZ + e * bES + bSO + o0;
    int m0 = blockIdx.x * 128;
    int tid = threadIdx.x;
    int tx = tid & 15, ty = tid >> 4;

    float acc[8][4];
    #pragma unroll
    for (int i = 0; i < 8; i++)
        #pragma unroll
        for (int j = 0; j < 4; j++) acc[i][j] = 0.f;

    for (int k0 = 0; k0 < 256; k0 += 16) {
        // A tile: 128x16 (512 float4s), 2 per thread, stored transposed
        #pragma unroll
        for (int i = 0; i < 2; i++) {
            int row = (tid >> 2) + i * 64;
            int c4  = (tid & 3) * 4;
            int m = m0 + row;
            float4 f = make_float4(0.f, 0.f, 0.f, 0.f);
            if (m < M) f = *(const float4*)(A + (long)m * 256 + k0 + c4);
            As[c4 + 0][row] = f.x; As[c4 + 1][row] = f.y;
            As[c4 + 2][row] = f.z; As[c4 + 3][row] = f.w;
        }
        // W tile: 64x16 (256 float4s), 1 per thread
        {
            int row = tid >> 2;
            int c4  = (tid & 3) * 4;
            float4 f = *(const float4*)(Wblk + row * 256 + k0 + c4);
            Bs[c4 + 0][row] = f.x; Bs[c4 + 1][row] = f.y;
            Bs[c4 + 2][row] = f.z; Bs[c4 + 3][row] = f.w;
        }
        __syncthreads();
        #pragma unroll
        for (int kk = 0; kk < 16; kk++) {
            float4 a0 = *(const float4*)&As[kk][ty * 8];
            float4 a1 = *(const float4*)&As[kk][ty * 8 + 4];
            float4 b0 = *(const float4*)&Bs[kk][tx * 4];
            float a[8] = {a0.x, a0.y, a0.z, a0.w, a1.x, a1.y, a1.z, a1.w};
            float b[4] = {b0.x, b0.y, b0.z, b0.w};
            #pragma unroll
            for (int i = 0; i < 8; i++)
                #pragma unroll
                for (int j = 0; j < 4; j++)
                    acc[i][j] = fmaf(a[i], b[j], acc[i][j]);
        }
        __syncthreads();
    }

    float4 bv = *(const float4*)(biasBlk + tx * 4);
    #pragma unroll
    for (int i = 0; i < 8; i++) {
        int m = m0 + ty * 8 + i;
        if (m < M) {
            float4 o = make_float4(acc[i][0] + bv.x, acc[i][1] + bv.y,
                                   acc[i][2] + bv.z, acc[i][3] + bv.w);
            *(float4*)(C + (long)m * ldc + n0 + tx * 4) = o;
        }
    }
}

// ---------------- attention: one block per (h, b, e) -----------------------
// Thread t (< 100) owns query row t; K/V streamed in 128-key smem chunks;
// online softmax in registers.
__global__ __launch_bounds__(128)
void attn_kernel() {
    __shared__ float Ks[128][32];
    __shared__ float Vs[128][32];
    int h = blockIdx.x, b = blockIdx.y, e = blockIdx.z;
    int t = threadIdx.x;
    const float scale = 0.17677669529663688f;  // 1/sqrt(32)

    float q[32], accv[32];
    float mloc = -INFINITY, lsum = 0.f;
    #pragma unroll
    for (int j = 0; j < 32; j++) { q[j] = 0.f; accv[j] = 0.f; }
    if (t < LQ) {
        const float* qp = g_Q + (long)(t * BB + b) * NEXP + e * D + h * HD;
        #pragma unroll
        for (int j = 0; j < 8; j++) {
            float4 f = *(const float4*)(qp + j * 4);
            q[j*4+0] = f.x * scale; q[j*4+1] = f.y * scale;
            q[j*4+2] = f.z * scale; q[j*4+3] = f.w * scale;
        }
    }

    for (int s0 = 0; s0 < LK; s0 += 128) {
        #pragma unroll
        for (int i = 0; i < 8; i++) {
            int idx = t + i * 128;          // float4 index 0..1023
            int row = idx >> 3;
            int c4  = (idx & 7) * 4;
            long base = (long)((s0 + row) * BB + b) * NEXP + e * D + h * HD + c4;
            *(float4*)&Ks[row][c4] = *(const float4*)(g_K + base);
            *(float4*)&Vs[row][c4] = *(const float4*)(g_V + base);
        }
        __syncthreads();
        if (t < LQ) {
            #pragma unroll 4
            for (int j = 0; j < 128; j++) {
                float s = 0.f;
                #pragma unroll
                for (int d = 0; d < 32; d++) s = fmaf(q[d], Ks[j][d], s);
                if (s > mloc) {
                    float f = __expf(mloc - s);   // expf(-inf)=0 on first hit
                    lsum *= f;
                    #pragma unroll
                    for (int d = 0; d < 32; d++) accv[d] *= f;
                    mloc = s;
                }
                float p = __expf(s - mloc);
                lsum += p;
                #pragma unroll
                for (int d = 0; d < 32; d++)
                    accv[d] = fmaf(p, Vs[j][d], accv[d]);
            }
        }
        __syncthreads();
    }

    if (t < LQ) {
        float inv = 1.f / lsum;
        float* cp = g_ctx + ((long)e * MQ + t * BB + b) * D + h * HD;
        #pragma unroll
        for (int j = 0; j < 8; j++) {
            float4 o = make_float4(accv[j*4+0]*inv, accv[j*4+1]*inv,
                                   accv[j*4+2]*inv, accv[j*4+3]*inv);
            *(float4*)(cp + j * 4) = o;
        }
    }
}

// ---------------- gated combine + residual + LayerNorm ---------------------
__global__ __launch_bounds__(256)
void combine_ln(const float* __restrict__ tgt,
                const float* __restrict__ gamma,
                const float* __restrict__ beta,
                float* __restrict__ out) {
    int m = blockIdx.x;
    int k = threadIdx.x;
    float g[NE];
    #pragma unroll
    for (int e = 0; e < NE; e++) g[e] = g_gate[m*NE + e];
    float x = tgt[(long)m * D + k];
    #pragma unroll
    for (int e = 0; e < NE; e++)
        x = fmaf(g[e], g_out[(long)e * MQ * D + (long)m * D + k], x);

    __shared__ float red[16];
    float s = x, s2 = x * x;
    #pragma unroll
    for (int o = 16; o > 0; o >>= 1) {
        s  += __shfl_xor_sync(0xffffffffu, s, o);
        s2 += __shfl_xor_sync(0xffffffffu, s2, o);
    }
    int wid = k >> 5, lane = k & 31;
    if (lane == 0) { red[wid] = s; red[8 + wid] = s2; }
    __syncthreads();
    if (k < 32) {
        float a  = (k < 8) ? red[k]     : 0.f;
        float b2 = (k < 8) ? red[8 + k] : 0.f;
        #pragma unroll
        for (int o = 4; o > 0; o >>= 1) {
            a  += __shfl_xor_sync(0xffffffffu, a,  o);
            b2 += __shfl_xor_sync(0xffffffffu, b2, o);
        }
        if (k == 0) { red[0] = a; red[1] = b2; }
    }
    __syncthreads();
    float mu  = red[0] * (1.f / D);
    float var = red[1] * (1.f / D) - mu * mu;
    float r = rsqrtf(var + 1e-5f);
    out[(long)m * D + k] = (x - mu) * r * gamma[k] + beta[k];
}

// ---------------- launch ----------------------------------------------------
extern "C" void kernel_launch(void* const* d_in, const int* in_sizes, int n_in,
                              void* d_out, int out_size) {
    const float* tgt    = (const float*)d_in[0];
    const float* memory = (const float*)d_in[1];
    const float* qpos   = (const float*)d_in[2];
    const float* pos    = (const float*)d_in[3];
    const float* w_in   = (const float*)d_in[4];
    const float* b_in   = (const float*)d_in[5];
    const float* w_out  = (const float*)d_in[6];
    const float* b_out  = (const float*)d_in[7];
    const float* w_gate = (const float*)d_in[8];
    const float* b_gate = (const float*)d_in[9];
    const float* gamma  = (const float*)d_in[10];
    const float* beta   = (const float*)d_in[11];

    float *pQemb, *pKemb, *pQ, *pK, *pV, *pCtx, *pOut;
    cudaGetSymbolAddress((void**)&pQemb, g_qemb);
    cudaGetSymbolAddress((void**)&pKemb, g_kemb);
    cudaGetSymbolAddress((void**)&pQ,    g_Q);
    cudaGetSymbolAddress((void**)&pK,    g_K);
    cudaGetSymbolAddress((void**)&pV,    g_V);
    cudaGetSymbolAddress((void**)&pCtx,  g_ctx);
    cudaGetSymbolAddress((void**)&pOut,  g_out);

    // positional adds
    addvec_kernel<<<(MQ*D/4 + 255)/256, 256>>>(tgt,    qpos, pQemb, MQ*D/4);
    addvec_kernel<<<(MK*D/4 + 255)/256, 256>>>(memory, pos,  pKemb, MK*D/4);

    // gate softmax
    gate_kernel<<<(MQ*32 + 127)/128, 128>>>(tgt, w_gate, b_gate);

    // QKV projections (W stacked across experts; sec = 0/1/2 inside w_in rows)
    sgemm256<<<dim3(13, 20, 1), 256>>>(pQemb,  w_in, b_in, pQ, MQ, NEXP,
                                       0, 0, 0, 0, 768*256, 0,      768, 0);
    sgemm256<<<dim3(128, 20, 1), 256>>>(pKemb, w_in, b_in, pK, MK, NEXP,
                                       0, 0, 0, 0, 768*256, 65536,  768, 256);
    sgemm256<<<dim3(128, 20, 1), 256>>>(memory, w_in, b_in, pV, MK, NEXP,
                                       0, 0, 0, 0, 768*256, 131072, 768, 512);

    // attention: (h, b, e) grid
    attn_kernel<<<dim3(NH, BB, NE), 128>>>();

    // output projection per expert (grid.z = expert)
    sgemm256<<<dim3(13, 4, NE), 256>>>(pCtx, w_out, b_out, pOut, MQ, D,
                                       MQ*D, 65536, 256, MQ*D, 0, 0, 0, 0);

    // gated combine + residual + LN
    combine_ln<<<MQ, 256>>>(tgt, gamma, beta, (float*)d_out);
}

// round 3
// speedup vs baseline: 2.1402x; 2.1402x over previous
#include <cuda_runtime.h>
#include <cuda_bf16.h>
#include <math.h>
#include <cstdint>

// Problem constants
#define D      256
#define NH     8
#define HD     32
#define NE     5
#define LQ     100
#define LK     1024
#define BB     16
#define MQ     (LQ*BB)      // 1600
#define MK     (LK*BB)      // 16384
#define NEXP   (NE*D)       // 1280
#define KCAT   768          // 3 * 256 (bf16 split-K concatenation)
#define KCH    64
#define NCHUNK (KCAT/KCH)   // 12

// ---------------- scratch (device globals) ---------------------------------
__device__ float g_Q[MQ*NEXP];
__device__ float g_K[MK*NEXP];
__device__ float g_V[MK*NEXP];
__device__ float g_gate[MQ*NE];
__device__ float g_ctx[NE*MQ*D];
__device__ float g_out[NE*MQ*D];

__device__ __nv_bfloat16 g_Aq[MQ*KCAT];
__device__ __nv_bfloat16 g_Ak[MK*KCAT];
__device__ __nv_bfloat16 g_Av[MK*KCAT];
__device__ __nv_bfloat16 g_Ac[NE*MQ*KCAT];
__device__ __nv_bfloat16 g_Wq[NEXP*KCAT];
__device__ __nv_bfloat16 g_Wk[NEXP*KCAT];
__device__ __nv_bfloat16 g_Wv[NEXP*KCAT];
__device__ __nv_bfloat16 g_Wo[NEXP*KCAT];

// ---------------- helpers ----------------------------------------------------
__device__ __forceinline__ uint32_t smem_u32(const void* p) {
    uint32_t a;
    asm("{ .reg .u64 t; cvta.to.shared.u64 t, %1; cvt.u32.u64 %0, t; }"
        : "=r"(a) : "l"(p));
    return a;
}

// SW128 swizzle of a byte offset within a tile of 128B rows
__device__ __forceinline__ uint32_t sw(uint32_t off) {
    return off ^ ((off >> 3) & 0x70);
}

__device__ __forceinline__ void cp16(uint32_t dst, const void* src, bool pred) {
    int sz = pred ? 16 : 0;
    asm volatile("cp.async.cg.shared.global [%0], [%1], 16, %2;"
                 :: "r"(dst), "l"(src), "r"(sz));
}
#define CP_COMMIT() asm volatile("cp.async.commit_group;" ::: "memory")
#define CP_WAIT1()  asm volatile("cp.async.wait_group 1;" ::: "memory")
#define CP_WAIT0()  asm volatile("cp.async.wait_group 0;" ::: "memory")

__device__ __forceinline__ void ldsm_x4(uint32_t* r, uint32_t addr) {
    asm volatile("ldmatrix.sync.aligned.m8n8.x4.shared.b16 {%0,%1,%2,%3}, [%4];"
                 : "=r"(r[0]), "=r"(r[1]), "=r"(r[2]), "=r"(r[3]) : "r"(addr));
}

__device__ __forceinline__ void mma16816(float* d, const uint32_t* a,
                                         const uint32_t* b) {
    asm volatile(
        "mma.sync.aligned.m16n8k16.row.col.f32.bf16.bf16.f32 "
        "{%0,%1,%2,%3}, {%4,%5,%6,%7}, {%8,%9}, {%0,%1,%2,%3};"
        : "+f"(d[0]), "+f"(d[1]), "+f"(d[2]), "+f"(d[3])
        : "r"(a[0]), "r"(a[1]), "r"(a[2]), "r"(a[3]), "r"(b[0]), "r"(b[1]));
}

// ---------------- split-bf16 conversions ------------------------------------
// A_cat row: [hi(256) | lo(256) | hi(256)]
__global__ void convert_act(const float* __restrict__ a,
                            const float* __restrict__ b,
                            __nv_bfloat16* __restrict__ out, int M) {
    int idx = blockIdx.x * blockDim.x + threadIdx.x;
    if (idx >= M * D) return;
    int m = idx >> 8, k = idx & 255;
    float x = a[idx];
    if (b) x += b[idx];
    __nv_bfloat16 hi = __float2bfloat16_rn(x);
    __nv_bfloat16 lo = __float2bfloat16_rn(x - __bfloat162float(hi));
    long base = (long)m * KCAT;
    out[base + k]       = hi;
    out[base + 256 + k] = lo;
    out[base + 512 + k] = hi;
}

// W_cat row: [hi(256) | hi(256) | lo(256)]
__global__ void convert_w(const float* __restrict__ w,
                          __nv_bfloat16* __restrict__ out,
                          int eStride, int sSO) {
    int idx = blockIdx.x * blockDim.x + threadIdx.x;   // over NEXP*256
    int n = idx >> 8, k = idx & 255;
    int e = n >> 8, o = n & 255;
    float x = w[(long)e * eStride + (long)(sSO + o) * 256 + k];
    __nv_bfloat16 hi = __float2bfloat16_rn(x);
    __nv_bfloat16 lo = __float2bfloat16_rn(x - __bfloat162float(hi));
    long base = (long)n * KCAT;
    out[base + k]       = hi;
    out[base + 256 + k] = hi;
    out[base + 512 + k] = lo;
}

// ---------------- HMMA GEMM: C[M x N] = A_cat @ W_cat^T + bias --------------
// CTA tile 128x128, 8 warps (2x4), warp tile 64x32, KCH=64, 2-stage cp.async.
// smem: stage s at s*32768 (A 16KB, B 16KB).
__global__ void __launch_bounds__(256)
gemm_mma(const __nv_bfloat16* __restrict__ A, const __nv_bfloat16* __restrict__ W,
         const float* __restrict__ bias, float* __restrict__ C,
         int M, int ldc,
         long aZ, long wZ, int bZ, long cZ, int bES, int bSO) {
    extern __shared__ char smc[];
    uint32_t smb = smem_u32(smc);
    int tid = threadIdx.x, wid = tid >> 5, lane = tid & 31;
    int z = blockIdx.z;
    A += z * aZ;
    C += z * cZ;
    int m0 = blockIdx.x * 128;
    int n0 = blockIdx.y * 128;
    const __nv_bfloat16* Wb = W + z * wZ + (long)n0 * KCAT;

    int wm = wid >> 2, wn = wid & 3;
    float acc[4][4][4];
    #pragma unroll
    for (int i = 0; i < 4; i++)
        #pragma unroll
        for (int j = 0; j < 4; j++)
            #pragma unroll
            for (int q = 0; q < 4; q++) acc[i][j][q] = 0.f;

    // issue chunk 0
    {
        int kc = 0;
        #pragma unroll
        for (int i = 0; i < 4; i++) {
            int idx = tid + i * 256, row = idx >> 3, seg = idx & 7;
            int m = m0 + row;
            cp16(smb + sw(row * 128 + seg * 16),
                 A + (long)m * KCAT + kc + seg * 8, m < M);
        }
        #pragma unroll
        for (int i = 0; i < 4; i++) {
            int idx = tid + i * 256, row = idx >> 3, seg = idx & 7;
            cp16(smb + 16384 + sw(row * 128 + seg * 16),
                 Wb + (long)row * KCAT + kc + seg * 8, true);
        }
        CP_COMMIT();
    }

    for (int c = 0; c < NCHUNK; c++) {
        if (c + 1 < NCHUNK) {
            int kc = (c + 1) * KCH;
            uint32_t st = smb + ((c + 1) & 1) * 32768;
            #pragma unroll
            for (int i = 0; i < 4; i++) {
                int idx = tid + i * 256, row = idx >> 3, seg = idx & 7;
                int m = m0 + row;
                cp16(st + sw(row * 128 + seg * 16),
                     A + (long)m * KCAT + kc + seg * 8, m < M);
            }
            #pragma unroll
            for (int i = 0; i < 4; i++) {
                int idx = tid + i * 256, row = idx >> 3, seg = idx & 7;
                cp16(st + 16384 + sw(row * 128 + seg * 16),
                     Wb + (long)row * KCAT + kc + seg * 8, true);
            }
            CP_COMMIT();
            CP_WAIT1();
        } else {
            CP_WAIT0();
        }
        __syncthreads();

        uint32_t stA = smb + (c & 1) * 32768;
        uint32_t stB = stA + 16384;
        #pragma unroll
        for (int ks = 0; ks < 4; ks++) {
            uint32_t a[4][4];
            #pragma unroll
            for (int mi = 0; mi < 4; mi++) {
                int r = wm * 64 + mi * 16 + (lane & 7) + ((lane >> 3) & 1) * 8;
                int cB = (ks * 16 + (lane >> 4) * 8) * 2;
                ldsm_x4(a[mi], stA + sw(r * 128 + cB));
            }
            uint32_t b[2][4];
            #pragma unroll
            for (int ni = 0; ni < 2; ni++) {
                int r = wn * 32 + ni * 16 + (lane & 7) + (lane >> 4) * 8;
                int cB = (ks * 16 + ((lane >> 3) & 1) * 8) * 2;
                ldsm_x4(b[ni], stB + sw(r * 128 + cB));
            }
            #pragma unroll
            for (int mi = 0; mi < 4; mi++) {
                #pragma unroll
                for (int nj = 0; nj < 4; nj++) {
                    mma16816(acc[mi][nj], a[mi], &b[nj >> 1][(nj & 1) * 2]);
                }
            }
        }
        __syncthreads();
    }

    // epilogue: bias + store
    int tq = lane >> 2, tr = lane & 3;
    #pragma unroll
    for (int mi = 0; mi < 4; mi++) {
        #pragma unroll
        for (int nj = 0; nj < 4; nj++) {
            int gm = m0 + wm * 64 + mi * 16 + tq;
            int lc = n0 + wn * 32 + nj * 8 + tr * 2;  // global col in [0, N)
            int e = lc >> 8;
            int bidx = z * bZ + e * bES + bSO + (lc & 255);
            float bx = __ldg(bias + bidx);
            float by = __ldg(bias + bidx + 1);
            if (gm < M) {
                float2 o = make_float2(acc[mi][nj][0] + bx, acc[mi][nj][1] + by);
                *(float2*)(C + (long)gm * ldc + lc) = o;
            }
            if (gm + 8 < M) {
                float2 o = make_float2(acc[mi][nj][2] + bx, acc[mi][nj][3] + by);
                *(float2*)(C + (long)(gm + 8) * ldc + lc) = o;
            }
        }
    }
}

// ---------------- gate: softmax over 5 experts per token -------------------
__global__ void gate_kernel(const float* __restrict__ tgt,
                            const float* __restrict__ wg,
                            const float* __restrict__ bg) {
    int warp = (blockIdx.x * blockDim.x + threadIdx.x) >> 5;
    int lane = threadIdx.x & 31;
    if (warp >= MQ) return;
    const float* x = tgt + warp * D;
    float logit[NE];
    #pragma unroll
    for (int e = 0; e < NE; e++) {
        float s = 0.f;
        #pragma unroll
        for (int k = lane; k < D; k += 32) s = fmaf(x[k], wg[e*D + k], s);
        #pragma unroll
        for (int o = 16; o > 0; o >>= 1) s += __shfl_xor_sync(0xffffffffu, s, o);
        logit[e] = s + bg[e];
    }
    if (lane == 0) {
        float mx = logit[0];
        #pragma unroll
        for (int e = 1; e < NE; e++) mx = fmaxf(mx, logit[e]);
        float p[NE], sum = 0.f;
        #pragma unroll
        for (int e = 0; e < NE; e++) { p[e] = __expf(logit[e] - mx); sum += p[e]; }
        float inv = 1.f / sum;
        #pragma unroll
        for (int e = 0; e < NE; e++) g_gate[warp*NE + e] = p[e] * inv;
    }
}

// ---------------- attention: one block per (h, b, e) -----------------------
__global__ void __launch_bounds__(128) attn_kernel() {
    __shared__ float Ks[128][32];
    __shared__ float Vs[128][32];
    int h = blockIdx.x, b = blockIdx.y, e = blockIdx.z;
    int t = threadIdx.x;
    const float scale = 0.17677669529663688f;  // 1/sqrt(32)

    float q[32], accv[32];
    float mloc = -INFINITY, lsum = 0.f;
    #pragma unroll
    for (int j = 0; j < 32; j++) { q[j] = 0.f; accv[j] = 0.f; }
    if (t < LQ) {
        const float* qp = g_Q + (long)(t * BB + b) * NEXP + e * D + h * HD;
        #pragma unroll
        for (int j = 0; j < 8; j++) {
            float4 f = *(const float4*)(qp + j * 4);
            q[j*4+0] = f.x * scale; q[j*4+1] = f.y * scale;
            q[j*4+2] = f.z * scale; q[j*4+3] = f.w * scale;
        }
    }

    for (int s0 = 0; s0 < LK; s0 += 128) {
        #pragma unroll
        for (int i = 0; i < 8; i++) {
            int idx = t + i * 128;
            int row = idx >> 3;
            int c4  = (idx & 7) * 4;
            long base = (long)((s0 + row) * BB + b) * NEXP + e * D + h * HD + c4;
            *(float4*)&Ks[row][c4] = *(const float4*)(g_K + base);
            *(float4*)&Vs[row][c4] = *(const float4*)(g_V + base);
        }
        __syncthreads();
        if (t < LQ) {
            #pragma unroll 4
            for (int j = 0; j < 128; j++) {
                float s = 0.f;
                #pragma unroll
                for (int d = 0; d < 32; d++) s = fmaf(q[d], Ks[j][d], s);
                if (s > mloc) {
                    float f = __expf(mloc - s);
                    lsum *= f;
                    #pragma unroll
                    for (int d = 0; d < 32; d++) accv[d] *= f;
                    mloc = s;
                }
                float p = __expf(s - mloc);
                lsum += p;
                #pragma unroll
                for (int d = 0; d < 32; d++)
                    accv[d] = fmaf(p, Vs[j][d], accv[d]);
            }
        }
        __syncthreads();
    }

    if (t < LQ) {
        float inv = 1.f / lsum;
        float* cp = g_ctx + ((long)e * MQ + t * BB + b) * D + h * HD;
        #pragma unroll
        for (int j = 0; j < 8; j++) {
            float4 o = make_float4(accv[j*4+0]*inv, accv[j*4+1]*inv,
                                   accv[j*4+2]*inv, accv[j*4+3]*inv);
            *(float4*)(cp + j * 4) = o;
        }
    }
}

// ---------------- gated combine + residual + LayerNorm ---------------------
__global__ void __launch_bounds__(256)
combine_ln(const float* __restrict__ tgt,
           const float* __restrict__ gamma,
           const float* __restrict__ beta,
           float* __restrict__ out) {
    int m = blockIdx.x;
    int k = threadIdx.x;
    float g[NE];
    #pragma unroll
    for (int e = 0; e < NE; e++) g[e] = g_gate[m*NE + e];
    float x = tgt[(long)m * D + k];
    #pragma unroll
    for (int e = 0; e < NE; e++)
        x = fmaf(g[e], g_out[(long)e * MQ * D + (long)m * D + k], x);

    __shared__ float red[16];
    float s = x, s2 = x * x;
    #pragma unroll
    for (int o = 16; o > 0; o >>= 1) {
        s  += __shfl_xor_sync(0xffffffffu, s, o);
        s2 += __shfl_xor_sync(0xffffffffu, s2, o);
    }
    int wid = k >> 5, lane = k & 31;
    if (lane == 0) { red[wid] = s; red[8 + wid] = s2; }
    __syncthreads();
    if (k < 32) {
        float a  = (k < 8) ? red[k]     : 0.f;
        float b2 = (k < 8) ? red[8 + k] : 0.f;
        #pragma unroll
        for (int o = 4; o > 0; o >>= 1) {
            a  += __shfl_xor_sync(0xffffffffu, a,  o);
            b2 += __shfl_xor_sync(0xffffffffu, b2, o);
        }
        if (k == 0) { red[0] = a; red[1] = b2; }
    }
    __syncthreads();
    float mu  = red[0] * (1.f / D);
    float var = red[1] * (1.f / D) - mu * mu;
    float r = rsqrtf(var + 1e-5f);
    out[(long)m * D + k] = (x - mu) * r * gamma[k] + beta[k];
}

// ---------------- launch ----------------------------------------------------
extern "C" void kernel_launch(void* const* d_in, const int* in_sizes, int n_in,
                              void* d_out, int out_size) {
    const float* tgt    = (const float*)d_in[0];
    const float* memory = (const float*)d_in[1];
    const float* qpos   = (const float*)d_in[2];
    const float* pos    = (const float*)d_in[3];
    const float* w_in   = (const float*)d_in[4];
    const float* b_in   = (const float*)d_in[5];
    const float* w_out  = (const float*)d_in[6];
    const float* b_out  = (const float*)d_in[7];
    const float* w_gate = (const float*)d_in[8];
    const float* b_gate = (const float*)d_in[9];
    const float* gamma  = (const float*)d_in[10];
    const float* beta   = (const float*)d_in[11];

    float *pQ, *pK, *pV, *pCtx, *pOut;
    __nv_bfloat16 *pAq, *pAk, *pAv, *pAc, *pWq, *pWk, *pWv, *pWo;
    cudaGetSymbolAddress((void**)&pQ,   g_Q);
    cudaGetSymbolAddress((void**)&pK,   g_K);
    cudaGetSymbolAddress((void**)&pV,   g_V);
    cudaGetSymbolAddress((void**)&pCtx, g_ctx);
    cudaGetSymbolAddress((void**)&pOut, g_out);
    cudaGetSymbolAddress((void**)&pAq,  g_Aq);
    cudaGetSymbolAddress((void**)&pAk,  g_Ak);
    cudaGetSymbolAddress((void**)&pAv,  g_Av);
    cudaGetSymbolAddress((void**)&pAc,  g_Ac);
    cudaGetSymbolAddress((void**)&pWq,  g_Wq);
    cudaGetSymbolAddress((void**)&pWk,  g_Wk);
    cudaGetSymbolAddress((void**)&pWv,  g_Wv);
    cudaGetSymbolAddress((void**)&pWo,  g_Wo);

    cudaFuncSetAttribute(gemm_mma, cudaFuncAttributeMaxDynamicSharedMemorySize, 65536);

    // operand conversions (hi/lo bf16 split, K-concatenated)
    convert_act<<<(MQ*D + 255)/256, 256>>>(tgt,    qpos,    pAq, MQ);
    convert_act<<<(MK*D + 255)/256, 256>>>(memory, pos,     pAk, MK);
    convert_act<<<(MK*D + 255)/256, 256>>>(memory, nullptr, pAv, MK);
    convert_w<<<NEXP, 256>>>(w_in,  pWq, 768*256, 0);
    convert_w<<<NEXP, 256>>>(w_in,  pWk, 768*256, 256);
    convert_w<<<NEXP, 256>>>(w_in,  pWv, 768*256, 512);
    convert_w<<<NEXP, 256>>>(w_out, pWo, 256*256, 0);

    gate_kernel<<<(MQ*32 + 127)/128, 128>>>(tgt, w_gate, b_gate);

    // QKV projections on HMMA tensor cores
    gemm_mma<<<dim3(13, 10, 1), 256, 65536>>>(pAq, pWq, b_in, pQ, MQ, NEXP,
                                              0, 0, 0, 0, 768, 0);
    gemm_mma<<<dim3(128, 10, 1), 256, 65536>>>(pAk, pWk, b_in, pK, MK, NEXP,
                                               0, 0, 0, 0, 768, 256);
    gemm_mma<<<dim3(128, 10, 1), 256, 65536>>>(pAv, pWv, b_in, pV, MK, NEXP,
                                               0, 0, 0, 0, 768, 512);

    // attention
    attn_kernel<<<dim3(NH, BB, NE), 128>>>();

    // out projection (per expert via grid.z)
    convert_act<<<(NE*MQ*D + 255)/256, 256>>>(pCtx, nullptr, pAc, NE*MQ);
    gemm_mma<<<dim3(13, 2, 5), 256, 65536>>>(pAc, pWo, b_out, pOut, MQ, D,
                                             (long)MQ*KCAT, (long)D*KCAT,
                                             D, (long)MQ*D, 0, 0);

    // gated combine + residual + LN
    combine_ln<<<MQ, 256>>>(tgt, gamma, beta, (float*)d_out);
}

// round 5
// speedup vs baseline: 3.6470x; 1.7040x over previous
#include <cuda_runtime.h>
#include <cuda_bf16.h>
#include <math.h>
#include <cstdint>

// Problem constants
#define D      256
#define NH     8
#define HD     32
#define NE     5
#define LQ     100
#define LK     1024
#define BB     16
#define MQ     (LQ*BB)      // 1600
#define MK     (LK*BB)      // 16384
#define NEXP   (NE*D)       // 1280
#define KCAT   768          // 3 * 256 (bf16 split-K concatenation)
#define KCH    64
#define NCHUNK (KCAT/KCH)   // 12

// ---------------- scratch (device globals) ---------------------------------
__device__ float g_Q[MQ*NEXP];
__device__ float g_K[MK*NEXP];
__device__ float g_V[MK*NEXP];
__device__ float g_gate[MQ*NE];
__device__ float g_ctx[NE*MQ*D];
__device__ float g_out[NE*MQ*D];

__device__ __nv_bfloat16 g_Aq[MQ*KCAT];
__device__ __nv_bfloat16 g_Ak[MK*KCAT];
__device__ __nv_bfloat16 g_Av[MK*KCAT];
__device__ __nv_bfloat16 g_Ac[NE*MQ*KCAT];
__device__ __nv_bfloat16 g_Wq[NEXP*KCAT];
__device__ __nv_bfloat16 g_Wk[NEXP*KCAT];
__device__ __nv_bfloat16 g_Wv[NEXP*KCAT];
__device__ __nv_bfloat16 g_Wo[NEXP*KCAT];

// ---------------- helpers ----------------------------------------------------
__device__ __forceinline__ uint32_t smem_u32(const void* p) {
    uint32_t a;
    asm("{ .reg .u64 t; cvta.to.shared.u64 t, %1; cvt.u32.u64 %0, t; }"
        : "=r"(a) : "l"(p));
    return a;
}

__device__ __forceinline__ uint32_t sw(uint32_t off) {
    return off ^ ((off >> 3) & 0x70);
}

__device__ __forceinline__ void cp16(uint32_t dst, const void* src, bool pred) {
    int sz = pred ? 16 : 0;
    asm volatile("cp.async.cg.shared.global [%0], [%1], 16, %2;"
                 :: "r"(dst), "l"(src), "r"(sz));
}
#define CP_COMMIT() asm volatile("cp.async.commit_group;" ::: "memory")
#define CP_WAIT1()  asm volatile("cp.async.wait_group 1;" ::: "memory")
#define CP_WAIT0()  asm volatile("cp.async.wait_group 0;" ::: "memory")

__device__ __forceinline__ void ldsm_x4(uint32_t* r, uint32_t addr) {
    asm volatile("ldmatrix.sync.aligned.m8n8.x4.shared.b16 {%0,%1,%2,%3}, [%4];"
                 : "=r"(r[0]), "=r"(r[1]), "=r"(r[2]), "=r"(r[3]) : "r"(addr));
}

__device__ __forceinline__ void ldsm_x4_t(uint32_t* r, uint32_t addr) {
    asm volatile("ldmatrix.sync.aligned.m8n8.x4.trans.shared.b16 {%0,%1,%2,%3}, [%4];"
                 : "=r"(r[0]), "=r"(r[1]), "=r"(r[2]), "=r"(r[3]) : "r"(addr));
}

__device__ __forceinline__ void mma16816(float* d, const uint32_t* a,
                                         const uint32_t* b) {
    asm volatile(
        "mma.sync.aligned.m16n8k16.row.col.f32.bf16.bf16.f32 "
        "{%0,%1,%2,%3}, {%4,%5,%6,%7}, {%8,%9}, {%0,%1,%2,%3};"
        : "+f"(d[0]), "+f"(d[1]), "+f"(d[2]), "+f"(d[3])
        : "r"(a[0]), "r"(a[1]), "r"(a[2]), "r"(a[3]), "r"(b[0]), "r"(b[1]));
}

// pack two fp32 into bf16x2: low half = x, high half = y
__device__ __forceinline__ uint32_t packbf2(float x, float y) {
    uint32_t d;
    asm("cvt.rn.bf16x2.f32 %0, %1, %2;" : "=r"(d) : "f"(y), "f"(x));
    return d;
}

// split (x,y) into hi bf16x2 and lo bf16x2 residuals
__device__ __forceinline__ void split2(float x, float y, uint32_t& hi, uint32_t& lo) {
    hi = packbf2(x, y);
    __nv_bfloat162 h = *(__nv_bfloat162*)&hi;
    lo = packbf2(x - __bfloat162float(h.x), y - __bfloat162float(h.y));
}

// ---------------- split-bf16 conversions ------------------------------------
// A_cat row: [hi(256) | lo(256) | hi(256)]
__global__ void convert_act(const float* __restrict__ a,
                            const float* __restrict__ b,
                            __nv_bfloat16* __restrict__ out, int M) {
    int idx = blockIdx.x * blockDim.x + threadIdx.x;
    if (idx >= M * D) return;
    int m = idx >> 8, k = idx & 255;
    float x = a[idx];
    if (b) x += b[idx];
    __nv_bfloat16 hi = __float2bfloat16_rn(x);
    __nv_bfloat16 lo = __float2bfloat16_rn(x - __bfloat162float(hi));
    long base = (long)m * KCAT;
    out[base + k]       = hi;
    out[base + 256 + k] = lo;
    out[base + 512 + k] = hi;
}

// fused K/V activation conversion: reads memory (+pos) once
__global__ void convert_kv(const float* __restrict__ mem,
                           const float* __restrict__ pos,
                           __nv_bfloat16* __restrict__ outK,
                           __nv_bfloat16* __restrict__ outV) {
    int idx = blockIdx.x * blockDim.x + threadIdx.x;
    if (idx >= MK * D) return;
    int m = idx >> 8, k = idx & 255;
    float xv = mem[idx];
    float xk = xv + pos[idx];
    long base = (long)m * KCAT;
    __nv_bfloat16 hk = __float2bfloat16_rn(xk);
    __nv_bfloat16 lk = __float2bfloat16_rn(xk - __bfloat162float(hk));
    outK[base + k] = hk; outK[base + 256 + k] = lk; outK[base + 512 + k] = hk;
    __nv_bfloat16 hv = __float2bfloat16_rn(xv);
    __nv_bfloat16 lv = __float2bfloat16_rn(xv - __bfloat162float(hv));
    outV[base + k] = hv; outV[base + 256 + k] = lv; outV[base + 512 + k] = hv;
}

// W_cat row: [hi(256) | hi(256) | lo(256)]
__global__ void convert_w(const float* __restrict__ w,
                          __nv_bfloat16* __restrict__ out,
                          int eStride, int sSO) {
    int idx = blockIdx.x * blockDim.x + threadIdx.x;   // over NEXP*256
    int n = idx >> 8, k = idx & 255;
    int e = n >> 8, o = n & 255;
    float x = w[(long)e * eStride + (long)(sSO + o) * 256 + k];
    __nv_bfloat16 hi = __float2bfloat16_rn(x);
    __nv_bfloat16 lo = __float2bfloat16_rn(x - __bfloat162float(hi));
    long base = (long)n * KCAT;
    out[base + k]       = hi;
    out[base + 256 + k] = hi;
    out[base + 512 + k] = lo;
}

// ---------------- HMMA GEMM: C[M x N] = A_cat @ W_cat^T + bias --------------
__global__ void __launch_bounds__(256)
gemm_mma(const __nv_bfloat16* __restrict__ A, const __nv_bfloat16* __restrict__ W,
         const float* __restrict__ bias, float* __restrict__ C,
         int M, int ldc,
         long aZ, long wZ, int bZ, long cZ, int bES, int bSO) {
    extern __shared__ char smc[];
    uint32_t smb = smem_u32(smc);
    int tid = threadIdx.x, wid = tid >> 5, lane = tid & 31;
    int z = blockIdx.z;
    A += z * aZ;
    C += z * cZ;
    int m0 = blockIdx.x * 128;
    int n0 = blockIdx.y * 128;
    const __nv_bfloat16* Wb = W + z * wZ + (long)n0 * KCAT;

    int wm = wid >> 2, wn = wid & 3;
    float acc[4][4][4];
    #pragma unroll
    for (int i = 0; i < 4; i++)
        #pragma unroll
        for (int j = 0; j < 4; j++)
            #pragma unroll
            for (int q = 0; q < 4; q++) acc[i][j][q] = 0.f;

    {
        int kc = 0;
        #pragma unroll
        for (int i = 0; i < 4; i++) {
            int idx = tid + i * 256, row = idx >> 3, seg = idx & 7;
            int m = m0 + row;
            cp16(smb + sw(row * 128 + seg * 16),
                 A + (long)m * KCAT + kc + seg * 8, m < M);
        }
        #pragma unroll
        for (int i = 0; i < 4; i++) {
            int idx = tid + i * 256, row = idx >> 3, seg = idx & 7;
            cp16(smb + 16384 + sw(row * 128 + seg * 16),
                 Wb + (long)row * KCAT + kc + seg * 8, true);
        }
        CP_COMMIT();
    }

    for (int c = 0; c < NCHUNK; c++) {
        if (c + 1 < NCHUNK) {
            int kc = (c + 1) * KCH;
            uint32_t st = smb + ((c + 1) & 1) * 32768;
            #pragma unroll
            for (int i = 0; i < 4; i++) {
                int idx = tid + i * 256, row = idx >> 3, seg = idx & 7;
                int m = m0 + row;
                cp16(st + sw(row * 128 + seg * 16),
                     A + (long)m * KCAT + kc + seg * 8, m < M);
            }
            #pragma unroll
            for (int i = 0; i < 4; i++) {
                int idx = tid + i * 256, row = idx >> 3, seg = idx & 7;
                cp16(st + 16384 + sw(row * 128 + seg * 16),
                     Wb + (long)row * KCAT + kc + seg * 8, true);
            }
            CP_COMMIT();
            CP_WAIT1();
        } else {
            CP_WAIT0();
        }
        __syncthreads();

        uint32_t stA = smb + (c & 1) * 32768;
        uint32_t stB = stA + 16384;
        #pragma unroll
        for (int ks = 0; ks < 4; ks++) {
            uint32_t a[4][4];
            #pragma unroll
            for (int mi = 0; mi < 4; mi++) {
                int r = wm * 64 + mi * 16 + (lane & 7) + ((lane >> 3) & 1) * 8;
                int cB = (ks * 16 + (lane >> 4) * 8) * 2;
                ldsm_x4(a[mi], stA + sw(r * 128 + cB));
            }
            uint32_t b[2][4];
            #pragma unroll
            for (int ni = 0; ni < 2; ni++) {
                int r = wn * 32 + ni * 16 + (lane & 7) + (lane >> 4) * 8;
                int cB = (ks * 16 + ((lane >> 3) & 1) * 8) * 2;
                ldsm_x4(b[ni], stB + sw(r * 128 + cB));
            }
            #pragma unroll
            for (int mi = 0; mi < 4; mi++) {
                #pragma unroll
                for (int nj = 0; nj < 4; nj++) {
                    mma16816(acc[mi][nj], a[mi], &b[nj >> 1][(nj & 1) * 2]);
                }
            }
        }
        __syncthreads();
    }

    int tq = lane >> 2, tr = lane & 3;
    #pragma unroll
    for (int mi = 0; mi < 4; mi++) {
        #pragma unroll
        for (int nj = 0; nj < 4; nj++) {
            int gm = m0 + wm * 64 + mi * 16 + tq;
            int lc = n0 + wn * 32 + nj * 8 + tr * 2;
            int e = lc >> 8;
            int bidx = z * bZ + e * bES + bSO + (lc & 255);
            float bx = __ldg(bias + bidx);
            float by = __ldg(bias + bidx + 1);
            if (gm < M) {
                float2 o = make_float2(acc[mi][nj][0] + bx, acc[mi][nj][1] + by);
                *(float2*)(C + (long)gm * ldc + lc) = o;
            }
            if (gm + 8 < M) {
                float2 o = make_float2(acc[mi][nj][2] + bx, acc[mi][nj][3] + by);
                *(float2*)(C + (long)(gm + 8) * ldc + lc) = o;
            }
        }
    }
}

// ---------------- gate: softmax over 5 experts per token -------------------
__global__ void gate_kernel(const float* __restrict__ tgt,
                            const float* __restrict__ wg,
                            const float* __restrict__ bg) {
    int warp = (blockIdx.x * blockDim.x + threadIdx.x) >> 5;
    int lane = threadIdx.x & 31;
    if (warp >= MQ) return;
    const float* x = tgt + warp * D;
    float logit[NE];
    #pragma unroll
    for (int e = 0; e < NE; e++) {
        float s = 0.f;
        #pragma unroll
        for (int k = lane; k < D; k += 32) s = fmaf(x[k], wg[e*D + k], s);
        #pragma unroll
        for (int o = 16; o > 0; o >>= 1) s += __shfl_xor_sync(0xffffffffu, s, o);
        logit[e] = s + bg[e];
    }
    if (lane == 0) {
        float mx = logit[0];
        #pragma unroll
        for (int e = 1; e < NE; e++) mx = fmaxf(mx, logit[e]);
        float p[NE], sum = 0.f;
        #pragma unroll
        for (int e = 0; e < NE; e++) { p[e] = __expf(logit[e] - mx); sum += p[e]; }
        float inv = 1.f / sum;
        #pragma unroll
        for (int e = 0; e < NE; e++) g_gate[warp*NE + e] = p[e] * inv;
    }
}

// ---------------- tensor-core flash attention -------------------------------
// CTA per (h, b, e); 4 warps; Lq padded to 128 (warp owns 32 rows).
#define QROW 208
#define VROW 80
#define SM_Q  0
#define SM_K  26624
#define SM_VH 53248
#define SM_VL 63488
#define ATT_SMEM 73728

__global__ void __launch_bounds__(128) attn_mma() {
    extern __shared__ char smc[];
    uint32_t smb = smem_u32(smc);
    int h = blockIdx.x, b = blockIdx.y, e = blockIdx.z;
    int tid = threadIdx.x, wid = tid >> 5, lane = tid & 31;
    const float scale = 0.17677669529663688f;  // 1/sqrt(32)

    // ---- load + split Q (row = tid), rows >= LQ zeroed -----------------
    {
        uint32_t qoff = smb + SM_Q + tid * QROW;
        if (tid < LQ) {
            const float4* qp = (const float4*)(g_Q + ((long)(tid * BB + b)) * NEXP
                                               + e * D + h * HD);
            #pragma unroll
            for (int j = 0; j < 8; j++) {
                float4 f = qp[j];
                uint32_t h01, l01, h23, l23;
                split2(f.x * scale, f.y * scale, h01, l01);
                split2(f.z * scale, f.w * scale, h23, l23);
                uint2 hv = make_uint2(h01, h23), lv = make_uint2(l01, l23);
                *(uint2*)(smc + (qoff - smb) + j * 8)       = hv;  // hi
                *(uint2*)(smc + (qoff - smb) + 64 + j * 8)  = lv;  // lo
                *(uint2*)(smc + (qoff - smb) + 128 + j * 8) = hv;  // hi
            }
        } else {
            uint2 z = make_uint2(0, 0);
            #pragma unroll
            for (int j = 0; j < 24; j++)
                *(uint2*)(smc + (qoff - smb) + j * 8) = z;
        }
    }

    // per-m-tile online-softmax state (2 m-tiles per warp)
    float mst[2][2], lst[2][2], O[2][4][4];
    #pragma unroll
    for (int mt = 0; mt < 2; mt++) {
        mst[mt][0] = -INFINITY; mst[mt][1] = -INFINITY;
        lst[mt][0] = 0.f; lst[mt][1] = 0.f;
        #pragma unroll
        for (int nt = 0; nt < 4; nt++)
            #pragma unroll
            for (int q = 0; q < 4; q++) O[mt][nt][q] = 0.f;
    }

    for (int s0 = 0; s0 < LK; s0 += 128) {
        __syncthreads();   // protect smem from previous iteration's readers
        // ---- load + split K chunk ([hi|hi|lo]) and V chunk (hi, lo) -----
        {
            long base = ((long)((s0 + tid) * BB + b)) * NEXP + e * D + h * HD;
            const float4* kp = (const float4*)(g_K + base);
            const float4* vp = (const float4*)(g_V + base);
            char* krow = smc + SM_K + tid * QROW;
            char* vhrow = smc + SM_VH + tid * VROW;
            char* vlrow = smc + SM_VL + tid * VROW;
            #pragma unroll
            for (int j = 0; j < 8; j++) {
                float4 f = kp[j];
                uint32_t h01, l01, h23, l23;
                split2(f.x, f.y, h01, l01);
                split2(f.z, f.w, h23, l23);
                uint2 hv = make_uint2(h01, h23), lv = make_uint2(l01, l23);
                *(uint2*)(krow + j * 8)       = hv;
                *(uint2*)(krow + 64 + j * 8)  = hv;
                *(uint2*)(krow + 128 + j * 8) = lv;
                f = vp[j];
                split2(f.x, f.y, h01, l01);
                split2(f.z, f.w, h23, l23);
                *(uint2*)(vhrow + j * 8) = make_uint2(h01, h23);
                *(uint2*)(vlrow + j * 8) = make_uint2(l01, l23);
            }
        }
        __syncthreads();

        #pragma unroll
        for (int mt = 0; mt < 2; mt++) {
            int m0 = wid * 32 + mt * 16;
            // Q A-fragments for 6 k-steps (96 cat cols)
            uint32_t aq[6][4];
            #pragma unroll
            for (int kk = 0; kk < 6; kk++)
                ldsm_x4(aq[kk], smb + SM_Q + (m0 + (lane & 15)) * QROW
                                 + kk * 32 + (lane >> 4) * 16);
            // scores S[16 n-tiles][4]
            float S[16][4];
            #pragma unroll
            for (int nt = 0; nt < 16; nt++)
                #pragma unroll
                for (int q = 0; q < 4; q++) S[nt][q] = 0.f;
            #pragma unroll
            for (int ng = 0; ng < 8; ng++) {
                #pragma unroll
                for (int kk = 0; kk < 6; kk++) {
                    uint32_t bk[4];
                    ldsm_x4(bk, smb + SM_K
                            + (ng * 16 + (lane & 7) + ((lane >> 4) << 3)) * QROW
                            + kk * 32 + (((lane >> 3) & 1) << 4));
                    mma16816(S[2 * ng],     aq[kk], bk);
                    mma16816(S[2 * ng + 1], aq[kk], bk + 2);
                }
            }
            // ---- online softmax ------------------------------------------
            float vA = -INFINITY, vB = -INFINITY;
            #pragma unroll
            for (int nt = 0; nt < 16; nt++) {
                vA = fmaxf(vA, fmaxf(S[nt][0], S[nt][1]));
                vB = fmaxf(vB, fmaxf(S[nt][2], S[nt][3]));
            }
            vA = fmaxf(vA, __shfl_xor_sync(0xffffffffu, vA, 1));
            vA = fmaxf(vA, __shfl_xor_sync(0xffffffffu, vA, 2));
            vB = fmaxf(vB, __shfl_xor_sync(0xffffffffu, vB, 1));
            vB = fmaxf(vB, __shfl_xor_sync(0xffffffffu, vB, 2));
            float mnA = fmaxf(mst[mt][0], vA), mnB = fmaxf(mst[mt][1], vB);
            float fA = __expf(mst[mt][0] - mnA), fB = __expf(mst[mt][1] - mnB);
            mst[mt][0] = mnA; mst[mt][1] = mnB;
            float sA = 0.f, sB = 0.f;
            #pragma unroll
            for (int nt = 0; nt < 16; nt++) {
                S[nt][0] = __expf(S[nt][0] - mnA);
                S[nt][1] = __expf(S[nt][1] - mnA);
                S[nt][2] = __expf(S[nt][2] - mnB);
                S[nt][3] = __expf(S[nt][3] - mnB);
                sA += S[nt][0] + S[nt][1];
                sB += S[nt][2] + S[nt][3];
            }
            // FIX (R4 bug): row sum is distributed over the 4 threads of the
            // quad (each holds 2 of 8 cols per n-tile) — reduce like the max.
            sA += __shfl_xor_sync(0xffffffffu, sA, 1);
            sA += __shfl_xor_sync(0xffffffffu, sA, 2);
            sB += __shfl_xor_sync(0xffffffffu, sB, 1);
            sB += __shfl_xor_sync(0xffffffffu, sB, 2);
            lst[mt][0] = lst[mt][0] * fA + sA;
            lst[mt][1] = lst[mt][1] * fB + sB;
            #pragma unroll
            for (int nt = 0; nt < 4; nt++) {
                O[mt][nt][0] *= fA; O[mt][nt][1] *= fA;
                O[mt][nt][2] *= fB; O[mt][nt][3] *= fB;
            }
            // ---- P @ V with (Phi,Plo) x (Vhi,Vlo) 3-term -------------------
            #pragma unroll
            for (int kt = 0; kt < 8; kt++) {
                uint32_t phi[4], plo[4];
                phi[0] = packbf2(S[2*kt][0],   S[2*kt][1]);
                phi[1] = packbf2(S[2*kt][2],   S[2*kt][3]);
                phi[2] = packbf2(S[2*kt+1][0], S[2*kt+1][1]);
                phi[3] = packbf2(S[2*kt+1][2], S[2*kt+1][3]);
                #pragma unroll
                for (int i = 0; i < 4; i++) {
                    __nv_bfloat162 hp = *(__nv_bfloat162*)&phi[i];
                    int nt = 2*kt + (i >> 1), q = (i & 1) * 2;
                    plo[i] = packbf2(S[nt][q]   - __bfloat162float(hp.x),
                                     S[nt][q+1] - __bfloat162float(hp.y));
                }
                uint32_t vrow = kt * 16 + (lane & 15);
                uint32_t bh0[4], bh1[4], bl0[4], bl1[4];
                ldsm_x4_t(bh0, smb + SM_VH + vrow * VROW + (lane >> 4) * 16);
                ldsm_x4_t(bh1, smb + SM_VH + vrow * VROW + 32 + (lane >> 4) * 16);
                ldsm_x4_t(bl0, smb + SM_VL + vrow * VROW + (lane >> 4) * 16);
                ldsm_x4_t(bl1, smb + SM_VL + vrow * VROW + 32 + (lane >> 4) * 16);
                mma16816(O[mt][0], phi, bh0); mma16816(O[mt][1], phi, bh0 + 2);
                mma16816(O[mt][2], phi, bh1); mma16816(O[mt][3], phi, bh1 + 2);
                mma16816(O[mt][0], plo, bh0); mma16816(O[mt][1], plo, bh0 + 2);
                mma16816(O[mt][2], plo, bh1); mma16816(O[mt][3], plo, bh1 + 2);
                mma16816(O[mt][0], phi, bl0); mma16816(O[mt][1], phi, bl0 + 2);
                mma16816(O[mt][2], phi, bl1); mma16816(O[mt][3], phi, bl1 + 2);
            }
        }
    }

    // ---- epilogue: normalize and store ctx ------------------------------
    int r = lane >> 2, c = (lane & 3) * 2;
    #pragma unroll
    for (int mt = 0; mt < 2; mt++) {
        float invA = 1.f / lst[mt][0];
        float invB = 1.f / lst[mt][1];
        int qA = wid * 32 + mt * 16 + r;
        int qB = qA + 8;
        #pragma unroll
        for (int nt = 0; nt < 4; nt++) {
            if (qA < LQ) {
                float* cp = g_ctx + ((long)e * MQ + qA * BB + b) * D + h * HD
                            + nt * 8 + c;
                *(float2*)cp = make_float2(O[mt][nt][0] * invA,
                                           O[mt][nt][1] * invA);
            }
            if (qB < LQ) {
                float* cp = g_ctx + ((long)e * MQ + qB * BB + b) * D + h * HD
                            + nt * 8 + c;
                *(float2*)cp = make_float2(O[mt][nt][2] * invB,
                                           O[mt][nt][3] * invB);
            }
        }
    }
}

// ---------------- gated combine + residual + LayerNorm ---------------------
__global__ void __launch_bounds__(256)
combine_ln(const float* __restrict__ tgt,
           const float* __restrict__ gamma,
           const float* __restrict__ beta,
           float* __restrict__ out) {
    int m = blockIdx.x;
    int k = threadIdx.x;
    float g[NE];
    #pragma unroll
    for (int e = 0; e < NE; e++) g[e] = g_gate[m*NE + e];
    float x = tgt[(long)m * D + k];
    #pragma unroll
    for (int e = 0; e < NE; e++)
        x = fmaf(g[e], g_out[(long)e * MQ * D + (long)m * D + k], x);

    __shared__ float red[16];
    float s = x, s2 = x * x;
    #pragma unroll
    for (int o = 16; o > 0; o >>= 1) {
        s  += __shfl_xor_sync(0xffffffffu, s, o);
        s2 += __shfl_xor_sync(0xffffffffu, s2, o);
    }
    int wid = k >> 5, lane = k & 31;
    if (lane == 0) { red[wid] = s; red[8 + wid] = s2; }
    __syncthreads();
    if (k < 32) {
        float a  = (k < 8) ? red[k]     : 0.f;
        float b2 = (k < 8) ? red[8 + k] : 0.f;
        #pragma unroll
        for (int o = 4; o > 0; o >>= 1) {
            a  += __shfl_xor_sync(0xffffffffu, a,  o);
            b2 += __shfl_xor_sync(0xffffffffu, b2, o);
        }
        if (k == 0) { red[0] = a; red[1] = b2; }
    }
    __syncthreads();
    float mu  = red[0] * (1.f / D);
    float var = red[1] * (1.f / D) - mu * mu;
    float r = rsqrtf(var + 1e-5f);
    out[(long)m * D + k] = (x - mu) * r * gamma[k] + beta[k];
}

// ---------------- launch ----------------------------------------------------
extern "C" void kernel_launch(void* const* d_in, const int* in_sizes, int n_in,
                              void* d_out, int out_size) {
    const float* tgt    = (const float*)d_in[0];
    const float* memory = (const float*)d_in[1];
    const float* qpos   = (const float*)d_in[2];
    const float* pos    = (const float*)d_in[3];
    const float* w_in   = (const float*)d_in[4];
    const float* b_in   = (const float*)d_in[5];
    const float* w_out  = (const float*)d_in[6];
    const float* b_out  = (const float*)d_in[7];
    const float* w_gate = (const float*)d_in[8];
    const float* b_gate = (const float*)d_in[9];
    const float* gamma  = (const float*)d_in[10];
    const float* beta   = (const float*)d_in[11];

    float *pQ, *pK, *pV, *pCtx, *pOut;
    __nv_bfloat16 *pAq, *pAk, *pAv, *pAc, *pWq, *pWk, *pWv, *pWo;
    cudaGetSymbolAddress((void**)&pQ,   g_Q);
    cudaGetSymbolAddress((void**)&pK,   g_K);
    cudaGetSymbolAddress((void**)&pV,   g_V);
    cudaGetSymbolAddress((void**)&pCtx, g_ctx);
    cudaGetSymbolAddress((void**)&pOut, g_out);
    cudaGetSymbolAddress((void**)&pAq,  g_Aq);
    cudaGetSymbolAddress((void**)&pAk,  g_Ak);
    cudaGetSymbolAddress((void**)&pAv,  g_Av);
    cudaGetSymbolAddress((void**)&pAc,  g_Ac);
    cudaGetSymbolAddress((void**)&pWq,  g_Wq);
    cudaGetSymbolAddress((void**)&pWk,  g_Wk);
    cudaGetSymbolAddress((void**)&pWv,  g_Wv);
    cudaGetSymbolAddress((void**)&pWo,  g_Wo);

    cudaFuncSetAttribute(gemm_mma, cudaFuncAttributeMaxDynamicSharedMemorySize, 65536);
    cudaFuncSetAttribute(attn_mma, cudaFuncAttributeMaxDynamicSharedMemorySize, ATT_SMEM);

    // operand conversions (hi/lo bf16 split, K-concatenated)
    convert_act<<<(MQ*D + 255)/256, 256>>>(tgt, qpos, pAq, MQ);
    convert_kv<<<(MK*D + 255)/256, 256>>>(memory, pos, pAk, pAv);
    convert_w<<<NEXP, 256>>>(w_in,  pWq, 768*256, 0);
    convert_w<<<NEXP, 256>>>(w_in,  pWk, 768*256, 256);
    convert_w<<<NEXP, 256>>>(w_in,  pWv, 768*256, 512);
    convert_w<<<NEXP, 256>>>(w_out, pWo, 256*256, 0);

    gate_kernel<<<(MQ*32 + 127)/128, 128>>>(tgt, w_gate, b_gate);

    // QKV projections on HMMA tensor cores
    gemm_mma<<<dim3(13, 10, 1), 256, 65536>>>(pAq, pWq, b_in, pQ, MQ, NEXP,
                                              0, 0, 0, 0, 768, 0);
    gemm_mma<<<dim3(128, 10, 1), 256, 65536>>>(pAk, pWk, b_in, pK, MK, NEXP,
                                               0, 0, 0, 0, 768, 256);
    gemm_mma<<<dim3(128, 10, 1), 256, 65536>>>(pAv, pWv, b_in, pV, MK, NEXP,
                                               0, 0, 0, 0, 768, 512);

    // tensor-core flash attention
    attn_mma<<<dim3(NH, BB, NE), 128, ATT_SMEM>>>();

    // out projection (per expert via grid.z)
    convert_act<<<(NE*MQ*D + 255)/256, 256>>>(pCtx, nullptr, pAc, NE*MQ);
    gemm_mma<<<dim3(13, 2, 5), 256, 65536>>>(pAc, pWo, b_out, pOut, MQ, D,
                                             (long)MQ*KCAT, (long)D*KCAT,
                                             D, (long)MQ*D, 0, 0);

    // gated combine + residual + LN
    combine_ln<<<MQ, 256>>>(tgt, gamma, beta, (float*)d_out);
}

// round 6
// speedup vs baseline: 3.6702x; 1.0064x over previous
#include <cuda_runtime.h>
#include <cuda_bf16.h>
#include <math.h>
#include <cstdint>

// Problem constants
#define D      256
#define NH     8
#define HD     32
#define NE     5
#define LQ     100
#define LK     1024
#define BB     16
#define MQ     (LQ*BB)      // 1600
#define MK     (LK*BB)      // 16384
#define NEXP   (NE*D)       // 1280
#define KCAT   768          // W cat: [hi|hi|lo]
#define KA     512          // A cat: [hi|lo] (hi chunks re-read for 3rd term)
#define NCHUNK 12

// ---------------- scratch (device globals) ---------------------------------
__device__ float g_Q[MQ*NEXP];
__device__ float g_K[MK*NEXP];
__device__ float g_V[MK*NEXP];
__device__ float g_gate[MQ*NE];
__device__ float g_ctx[NE*MQ*D];
__device__ float g_out[NE*MQ*D];

__device__ __nv_bfloat16 g_Aq[MQ*KA];
__device__ __nv_bfloat16 g_Ak[MK*KA];
__device__ __nv_bfloat16 g_Av[MK*KA];
__device__ __nv_bfloat16 g_Ac[NE*MQ*KA];
__device__ __nv_bfloat16 g_Wq[NEXP*KCAT];
__device__ __nv_bfloat16 g_Wk[NEXP*KCAT];
__device__ __nv_bfloat16 g_Wv[NEXP*KCAT];
__device__ __nv_bfloat16 g_Wo[NEXP*KCAT];

// ---------------- helpers ----------------------------------------------------
__device__ __forceinline__ uint32_t smem_u32(const void* p) {
    uint32_t a;
    asm("{ .reg .u64 t; cvta.to.shared.u64 t, %1; cvt.u32.u64 %0, t; }"
        : "=r"(a) : "l"(p));
    return a;
}

__device__ __forceinline__ uint32_t sw(uint32_t off) {
    return off ^ ((off >> 3) & 0x70);
}

__device__ __forceinline__ void cp16(uint32_t dst, const void* src, bool pred) {
    int sz = pred ? 16 : 0;
    asm volatile("cp.async.cg.shared.global [%0], [%1], 16, %2;"
                 :: "r"(dst), "l"(src), "r"(sz));
}
#define CP_COMMIT() asm volatile("cp.async.commit_group;" ::: "memory")
#define CP_WAIT2()  asm volatile("cp.async.wait_group 2;" ::: "memory")
#define CP_WAIT1()  asm volatile("cp.async.wait_group 1;" ::: "memory")
#define CP_WAIT0()  asm volatile("cp.async.wait_group 0;" ::: "memory")

__device__ __forceinline__ void ldsm_x4(uint32_t* r, uint32_t addr) {
    asm volatile("ldmatrix.sync.aligned.m8n8.x4.shared.b16 {%0,%1,%2,%3}, [%4];"
                 : "=r"(r[0]), "=r"(r[1]), "=r"(r[2]), "=r"(r[3]) : "r"(addr));
}

__device__ __forceinline__ void ldsm_x4_t(uint32_t* r, uint32_t addr) {
    asm volatile("ldmatrix.sync.aligned.m8n8.x4.trans.shared.b16 {%0,%1,%2,%3}, [%4];"
                 : "=r"(r[0]), "=r"(r[1]), "=r"(r[2]), "=r"(r[3]) : "r"(addr));
}

__device__ __forceinline__ void mma16816(float* d, const uint32_t* a,
                                         const uint32_t* b) {
    asm volatile(
        "mma.sync.aligned.m16n8k16.row.col.f32.bf16.bf16.f32 "
        "{%0,%1,%2,%3}, {%4,%5,%6,%7}, {%8,%9}, {%0,%1,%2,%3};"
        : "+f"(d[0]), "+f"(d[1]), "+f"(d[2]), "+f"(d[3])
        : "r"(a[0]), "r"(a[1]), "r"(a[2]), "r"(a[3]), "r"(b[0]), "r"(b[1]));
}

__device__ __forceinline__ uint32_t packbf2(float x, float y) {
    uint32_t d;
    asm("cvt.rn.bf16x2.f32 %0, %1, %2;" : "=r"(d) : "f"(y), "f"(x));
    return d;
}

__device__ __forceinline__ void split2(float x, float y, uint32_t& hi, uint32_t& lo) {
    hi = packbf2(x, y);
    __nv_bfloat162 h = *(__nv_bfloat162*)&hi;
    lo = packbf2(x - __bfloat162float(h.x), y - __bfloat162float(h.y));
}

// ---------------- split-bf16 conversions (vectorized) -----------------------
// A row layout: [hi(256) | lo(256)]
__global__ void convert_act(const float* __restrict__ a,
                            const float* __restrict__ b,
                            __nv_bfloat16* __restrict__ out, int M) {
    int idx = blockIdx.x * blockDim.x + threadIdx.x;   // over M*64 float4s
    if (idx >= M * 64) return;
    int m = idx >> 6, k4 = (idx & 63) << 2;
    float4 f = *(const float4*)(a + (long)idx * 4);
    if (b) {
        float4 g = *(const float4*)(b + (long)idx * 4);
        f.x += g.x; f.y += g.y; f.z += g.z; f.w += g.w;
    }
    uint32_t h01, l01, h23, l23;
    split2(f.x, f.y, h01, l01);
    split2(f.z, f.w, h23, l23);
    long base = (long)m * KA + k4;
    *(uint2*)(out + base)       = make_uint2(h01, h23);
    *(uint2*)(out + base + 256) = make_uint2(l01, l23);
}

// fused K/V conversion: reads memory (+pos) once
__global__ void convert_kv(const float* __restrict__ mem,
                           const float* __restrict__ pos,
                           __nv_bfloat16* __restrict__ outK,
                           __nv_bfloat16* __restrict__ outV) {
    int idx = blockIdx.x * blockDim.x + threadIdx.x;
    if (idx >= MK * 64) return;
    int m = idx >> 6, k4 = (idx & 63) << 2;
    float4 v = *(const float4*)(mem + (long)idx * 4);
    float4 p = *(const float4*)(pos + (long)idx * 4);
    long base = (long)m * KA + k4;
    uint32_t h01, l01, h23, l23;
    split2(v.x + p.x, v.y + p.y, h01, l01);
    split2(v.z + p.z, v.w + p.w, h23, l23);
    *(uint2*)(outK + base)       = make_uint2(h01, h23);
    *(uint2*)(outK + base + 256) = make_uint2(l01, l23);
    split2(v.x, v.y, h01, l01);
    split2(v.z, v.w, h23, l23);
    *(uint2*)(outV + base)       = make_uint2(h01, h23);
    *(uint2*)(outV + base + 256) = make_uint2(l01, l23);
}

// all four weight tensors in one launch; W row: [hi|hi|lo]
__global__ void convert_w_all(const float* __restrict__ w_in,
                              const float* __restrict__ w_out,
                              __nv_bfloat16* __restrict__ oq,
                              __nv_bfloat16* __restrict__ ok,
                              __nv_bfloat16* __restrict__ ov,
                              __nv_bfloat16* __restrict__ oo) {
    int idx = blockIdx.x * blockDim.x + threadIdx.x;   // over NEXP*64
    if (idx >= NEXP * 64) return;
    int n = idx >> 6, k4 = (idx & 63) << 2;
    int e = n >> 8, o = n & 255;
    long base = (long)n * KCAT + k4;
    __nv_bfloat16* dsts[3] = {oq, ok, ov};
    #pragma unroll
    for (int sec = 0; sec < 3; sec++) {
        float4 f = *(const float4*)(w_in + ((long)e * 768 + sec * 256 + o) * 256 + k4);
        uint32_t h01, l01, h23, l23;
        split2(f.x, f.y, h01, l01);
        split2(f.z, f.w, h23, l23);
        __nv_bfloat16* d = dsts[sec];
        *(uint2*)(d + base)       = make_uint2(h01, h23);
        *(uint2*)(d + base + 256) = make_uint2(h01, h23);
        *(uint2*)(d + base + 512) = make_uint2(l01, l23);
    }
    {
        float4 f = *(const float4*)(w_out + ((long)e * 256 + o) * 256 + k4);
        uint32_t h01, l01, h23, l23;
        split2(f.x, f.y, h01, l01);
        split2(f.z, f.w, h23, l23);
        *(uint2*)(oo + base)       = make_uint2(h01, h23);
        *(uint2*)(oo + base + 256) = make_uint2(h01, h23);
        *(uint2*)(oo + base + 512) = make_uint2(l01, l23);
    }
}

// ---------------- HMMA GEMM: 256x128 tile, 512 thr, 3-stage pipeline --------
#define TM 256
#define TN 128
#define STG 49152
#define GEMM_SMEM (3*STG)

__device__ __forceinline__ void gemm_issue(uint32_t smb, int c,
                                           const __nv_bfloat16* A,
                                           const __nv_bfloat16* Wb,
                                           int m0, int M, int tid) {
    uint32_t st = smb + (c % 3) * STG;
    // A chunk source: chunks 0-3 hi, 4-7 lo, 8-11 hi again
    int ko = (c < 4) ? c * 64 : (c < 8) ? 256 + (c - 4) * 64 : (c - 8) * 64;
    int kw = c * 64;
    #pragma unroll
    for (int i = 0; i < 4; i++) {
        int idx = tid + i * 512, row = idx >> 3, seg = idx & 7;
        int m = m0 + row;
        cp16(st + sw(row * 128 + seg * 16),
             A + (long)m * KA + ko + seg * 8, m < M);
    }
    #pragma unroll
    for (int i = 0; i < 2; i++) {
        int idx = tid + i * 512, row = idx >> 3, seg = idx & 7;
        cp16(st + TM * 128 + sw(row * 128 + seg * 16),
             Wb + (long)row * KCAT + kw + seg * 8, true);
    }
    CP_COMMIT();
}

__global__ void __launch_bounds__(512)
gemm_mma(const __nv_bfloat16* __restrict__ A, const __nv_bfloat16* __restrict__ W,
         const float* __restrict__ bias, float* __restrict__ C,
         int M, int ldc,
         long aZ, long wZ, int bZ, long cZ, int bES, int bSO) {
    extern __shared__ char smc[];
    uint32_t smb = smem_u32(smc);
    int tid = threadIdx.x, wid = tid >> 5, lane = tid & 31;
    int z = blockIdx.z;
    A += z * aZ;
    C += z * cZ;
    int m0 = blockIdx.x * TM;
    int n0 = blockIdx.y * TN;
    const __nv_bfloat16* Wb = W + z * wZ + (long)n0 * KCAT;

    int wm = wid >> 2, wn = wid & 3;
    float acc[4][4][4];
    #pragma unroll
    for (int i = 0; i < 4; i++)
        #pragma unroll
        for (int j = 0; j < 4; j++)
            #pragma unroll
            for (int q = 0; q < 4; q++) acc[i][j][q] = 0.f;

    gemm_issue(smb, 0, A, Wb, m0, M, tid);
    gemm_issue(smb, 1, A, Wb, m0, M, tid);

    for (int c = 0; c < NCHUNK; c++) {
        if (c + 2 < NCHUNK) { gemm_issue(smb, c + 2, A, Wb, m0, M, tid); CP_WAIT2(); }
        else if (c + 1 < NCHUNK) { CP_WAIT1(); }
        else { CP_WAIT0(); }
        __syncthreads();

        uint32_t stA = smb + (c % 3) * STG;
        uint32_t stB = stA + TM * 128;
        #pragma unroll
        for (int ks = 0; ks < 4; ks++) {
            uint32_t a[4][4];
            #pragma unroll
            for (int mi = 0; mi < 4; mi++) {
                int r = wm * 64 + mi * 16 + (lane & 7) + ((lane >> 3) & 1) * 8;
                int cB = (ks * 16 + (lane >> 4) * 8) * 2;
                ldsm_x4(a[mi], stA + sw(r * 128 + cB));
            }
            uint32_t b[2][4];
            #pragma unroll
            for (int ni = 0; ni < 2; ni++) {
                int r = wn * 32 + ni * 16 + (lane & 7) + (lane >> 4) * 8;
                int cB = (ks * 16 + ((lane >> 3) & 1) * 8) * 2;
                ldsm_x4(b[ni], stB + sw(r * 128 + cB));
            }
            #pragma unroll
            for (int mi = 0; mi < 4; mi++) {
                #pragma unroll
                for (int nj = 0; nj < 4; nj++) {
                    mma16816(acc[mi][nj], a[mi], &b[nj >> 1][(nj & 1) * 2]);
                }
            }
        }
        __syncthreads();
    }

    int tq = lane >> 2, tr = lane & 3;
    #pragma unroll
    for (int mi = 0; mi < 4; mi++) {
        #pragma unroll
        for (int nj = 0; nj < 4; nj++) {
            int gm = m0 + wm * 64 + mi * 16 + tq;
            int lc = n0 + wn * 32 + nj * 8 + tr * 2;
            int e = lc >> 8;
            int bidx = z * bZ + e * bES + bSO + (lc & 255);
            float bx = __ldg(bias + bidx);
            float by = __ldg(bias + bidx + 1);
            if (gm < M) {
                float2 o = make_float2(acc[mi][nj][0] + bx, acc[mi][nj][1] + by);
                *(float2*)(C + (long)gm * ldc + lc) = o;
            }
            if (gm + 8 < M) {
                float2 o = make_float2(acc[mi][nj][2] + bx, acc[mi][nj][3] + by);
                *(float2*)(C + (long)(gm + 8) * ldc + lc) = o;
            }
        }
    }
}

// ---------------- gate: softmax over 5 experts per token -------------------
__global__ void gate_kernel(const float* __restrict__ tgt,
                            const float* __restrict__ wg,
                            const float* __restrict__ bg) {
    int warp = (blockIdx.x * blockDim.x + threadIdx.x) >> 5;
    int lane = threadIdx.x & 31;
    if (warp >= MQ) return;
    const float* x = tgt + warp * D;
    float logit[NE];
    #pragma unroll
    for (int e = 0; e < NE; e++) {
        float s = 0.f;
        #pragma unroll
        for (int k = lane; k < D; k += 32) s = fmaf(x[k], wg[e*D + k], s);
        #pragma unroll
        for (int o = 16; o > 0; o >>= 1) s += __shfl_xor_sync(0xffffffffu, s, o);
        logit[e] = s + bg[e];
    }
    if (lane == 0) {
        float mx = logit[0];
        #pragma unroll
        for (int e = 1; e < NE; e++) mx = fmaxf(mx, logit[e]);
        float p[NE], sum = 0.f;
        #pragma unroll
        for (int e = 0; e < NE; e++) { p[e] = __expf(logit[e] - mx); sum += p[e]; }
        float inv = 1.f / sum;
        #pragma unroll
        for (int e = 0; e < NE; e++) g_gate[warp*NE + e] = p[e] * inv;
    }
}

// ---------------- tensor-core flash attention -------------------------------
#define QROW 208
#define VROW 80
#define SM_Q  0
#define SM_K  26624
#define SM_VH 53248
#define SM_VL 63488
#define ATT_SMEM 73728

__global__ void __launch_bounds__(128) attn_mma() {
    extern __shared__ char smc[];
    uint32_t smb = smem_u32(smc);
    int h = blockIdx.x, b = blockIdx.y, e = blockIdx.z;
    int tid = threadIdx.x, wid = tid >> 5, lane = tid & 31;
    const float scale = 0.17677669529663688f;  // 1/sqrt(32)

    {
        uint32_t qoff = smb + SM_Q + tid * QROW;
        if (tid < LQ) {
            const float4* qp = (const float4*)(g_Q + ((long)(tid * BB + b)) * NEXP
                                               + e * D + h * HD);
            #pragma unroll
            for (int j = 0; j < 8; j++) {
                float4 f = qp[j];
                uint32_t h01, l01, h23, l23;
                split2(f.x * scale, f.y * scale, h01, l01);
                split2(f.z * scale, f.w * scale, h23, l23);
                uint2 hv = make_uint2(h01, h23), lv = make_uint2(l01, l23);
                *(uint2*)(smc + (qoff - smb) + j * 8)       = hv;
                *(uint2*)(smc + (qoff - smb) + 64 + j * 8)  = lv;
                *(uint2*)(smc + (qoff - smb) + 128 + j * 8) = hv;
            }
        } else {
            uint2 z = make_uint2(0, 0);
            #pragma unroll
            for (int j = 0; j < 24; j++)
                *(uint2*)(smc + (qoff - smb) + j * 8) = z;
        }
    }

    float mst[2][2], lst[2][2], O[2][4][4];
    #pragma unroll
    for (int mt = 0; mt < 2; mt++) {
        mst[mt][0] = -INFINITY; mst[mt][1] = -INFINITY;
        lst[mt][0] = 0.f; lst[mt][1] = 0.f;
        #pragma unroll
        for (int nt = 0; nt < 4; nt++)
            #pragma unroll
            for (int q = 0; q < 4; q++) O[mt][nt][q] = 0.f;
    }

    for (int s0 = 0; s0 < LK; s0 += 128) {
        __syncthreads();
        {
            long base = ((long)((s0 + tid) * BB + b)) * NEXP + e * D + h * HD;
            const float4* kp = (const float4*)(g_K + base);
            const float4* vp = (const float4*)(g_V + base);
            char* krow = smc + SM_K + tid * QROW;
            char* vhrow = smc + SM_VH + tid * VROW;
            char* vlrow = smc + SM_VL + tid * VROW;
            #pragma unroll
            for (int j = 0; j < 8; j++) {
                float4 f = kp[j];
                uint32_t h01, l01, h23, l23;
                split2(f.x, f.y, h01, l01);
                split2(f.z, f.w, h23, l23);
                uint2 hv = make_uint2(h01, h23), lv = make_uint2(l01, l23);
                *(uint2*)(krow + j * 8)       = hv;
                *(uint2*)(krow + 64 + j * 8)  = hv;
                *(uint2*)(krow + 128 + j * 8) = lv;
                f = vp[j];
                split2(f.x, f.y, h01, l01);
                split2(f.z, f.w, h23, l23);
                *(uint2*)(vhrow + j * 8) = make_uint2(h01, h23);
                *(uint2*)(vlrow + j * 8) = make_uint2(l01, l23);
            }
        }
        __syncthreads();

        #pragma unroll
        for (int mt = 0; mt < 2; mt++) {
            int m0 = wid * 32 + mt * 16;
            uint32_t aq[6][4];
            #pragma unroll
            for (int kk = 0; kk < 6; kk++)
                ldsm_x4(aq[kk], smb + SM_Q + (m0 + (lane & 15)) * QROW
                                 + kk * 32 + (lane >> 4) * 16);
            float S[16][4];
            #pragma unroll
            for (int nt = 0; nt < 16; nt++)
                #pragma unroll
                for (int q = 0; q < 4; q++) S[nt][q] = 0.f;
            #pragma unroll
            for (int ng = 0; ng < 8; ng++) {
                #pragma unroll
                for (int kk = 0; kk < 6; kk++) {
                    uint32_t bk[4];
                    ldsm_x4(bk, smb + SM_K
                            + (ng * 16 + (lane & 7) + ((lane >> 4) << 3)) * QROW
                            + kk * 32 + (((lane >> 3) & 1) << 4));
                    mma16816(S[2 * ng],     aq[kk], bk);
                    mma16816(S[2 * ng + 1], aq[kk], bk + 2);
                }
            }
            float vA = -INFINITY, vB = -INFINITY;
            #pragma unroll
            for (int nt = 0; nt < 16; nt++) {
                vA = fmaxf(vA, fmaxf(S[nt][0], S[nt][1]));
                vB = fmaxf(vB, fmaxf(S[nt][2], S[nt][3]));
            }
            vA = fmaxf(vA, __shfl_xor_sync(0xffffffffu, vA, 1));
            vA = fmaxf(vA, __shfl_xor_sync(0xffffffffu, vA, 2));
            vB = fmaxf(vB, __shfl_xor_sync(0xffffffffu, vB, 1));
            vB = fmaxf(vB, __shfl_xor_sync(0xffffffffu, vB, 2));
            float mnA = fmaxf(mst[mt][0], vA), mnB = fmaxf(mst[mt][1], vB);
            float fA = __expf(mst[mt][0] - mnA), fB = __expf(mst[mt][1] - mnB);
            mst[mt][0] = mnA; mst[mt][1] = mnB;
            float sA = 0.f, sB = 0.f;
            #pragma unroll
            for (int nt = 0; nt < 16; nt++) {
                S[nt][0] = __expf(S[nt][0] - mnA);
                S[nt][1] = __expf(S[nt][1] - mnA);
                S[nt][2] = __expf(S[nt][2] - mnB);
                S[nt][3] = __expf(S[nt][3] - mnB);
                sA += S[nt][0] + S[nt][1];
                sB += S[nt][2] + S[nt][3];
            }
            sA += __shfl_xor_sync(0xffffffffu, sA, 1);
            sA += __shfl_xor_sync(0xffffffffu, sA, 2);
            sB += __shfl_xor_sync(0xffffffffu, sB, 1);
            sB += __shfl_xor_sync(0xffffffffu, sB, 2);
            lst[mt][0] = lst[mt][0] * fA + sA;
            lst[mt][1] = lst[mt][1] * fB + sB;
            #pragma unroll
            for (int nt = 0; nt < 4; nt++) {
                O[mt][nt][0] *= fA; O[mt][nt][1] *= fA;
                O[mt][nt][2] *= fB; O[mt][nt][3] *= fB;
            }
            #pragma unroll
            for (int kt = 0; kt < 8; kt++) {
                uint32_t phi[4], plo[4];
                phi[0] = packbf2(S[2*kt][0],   S[2*kt][1]);
                phi[1] = packbf2(S[2*kt][2],   S[2*kt][3]);
                phi[2] = packbf2(S[2*kt+1][0], S[2*kt+1][1]);
                phi[3] = packbf2(S[2*kt+1][2], S[2*kt+1][3]);
                #pragma unroll
                for (int i = 0; i < 4; i++) {
                    __nv_bfloat162 hp = *(__nv_bfloat162*)&phi[i];
                    int nt = 2*kt + (i >> 1), q = (i & 1) * 2;
                    plo[i] = packbf2(S[nt][q]   - __bfloat162float(hp.x),
                                     S[nt][q+1] - __bfloat162float(hp.y));
                }
                uint32_t vrow = kt * 16 + (lane & 15);
                uint32_t bh0[4], bh1[4], bl0[4], bl1[4];
                ldsm_x4_t(bh0, smb + SM_VH + vrow * VROW + (lane >> 4) * 16);
                ldsm_x4_t(bh1, smb + SM_VH + vrow * VROW + 32 + (lane >> 4) * 16);
                ldsm_x4_t(bl0, smb + SM_VL + vrow * VROW + (lane >> 4) * 16);
                ldsm_x4_t(bl1, smb + SM_VL + vrow * VROW + 32 + (lane >> 4) * 16);
                mma16816(O[mt][0], phi, bh0); mma16816(O[mt][1], phi, bh0 + 2);
                mma16816(O[mt][2], phi, bh1); mma16816(O[mt][3], phi, bh1 + 2);
                mma16816(O[mt][0], plo, bh0); mma16816(O[mt][1], plo, bh0 + 2);
                mma16816(O[mt][2], plo, bh1); mma16816(O[mt][3], plo, bh1 + 2);
                mma16816(O[mt][0], phi, bl0); mma16816(O[mt][1], phi, bl0 + 2);
                mma16816(O[mt][2], phi, bl1); mma16816(O[mt][3], phi, bl1 + 2);
            }
        }
    }

    int r = lane >> 2, c = (lane & 3) * 2;
    #pragma unroll
    for (int mt = 0; mt < 2; mt++) {
        float invA = 1.f / lst[mt][0];
        float invB = 1.f / lst[mt][1];
        int qA = wid * 32 + mt * 16 + r;
        int qB = qA + 8;
        #pragma unroll
        for (int nt = 0; nt < 4; nt++) {
            if (qA < LQ) {
                float* cp = g_ctx + ((long)e * MQ + qA * BB + b) * D + h * HD
                            + nt * 8 + c;
                *(float2*)cp = make_float2(O[mt][nt][0] * invA,
                                           O[mt][nt][1] * invA);
            }
            if (qB < LQ) {
                float* cp = g_ctx + ((long)e * MQ + qB * BB + b) * D + h * HD
                            + nt * 8 + c;
                *(float2*)cp = make_float2(O[mt][nt][2] * invB,
                                           O[mt][nt][3] * invB);
            }
        }
    }
}

// ---------------- gated combine + residual + LayerNorm ---------------------
__global__ void __launch_bounds__(256)
combine_ln(const float* __restrict__ tgt,
           const float* __restrict__ gamma,
           const float* __restrict__ beta,
           float* __restrict__ out) {
    int m = blockIdx.x;
    int k = threadIdx.x;
    float g[NE];
    #pragma unroll
    for (int e = 0; e < NE; e++) g[e] = g_gate[m*NE + e];
    float x = tgt[(long)m * D + k];
    #pragma unroll
    for (int e = 0; e < NE; e++)
        x = fmaf(g[e], g_out[(long)e * MQ * D + (long)m * D + k], x);

    __shared__ float red[16];
    float s = x, s2 = x * x;
    #pragma unroll
    for (int o = 16; o > 0; o >>= 1) {
        s  += __shfl_xor_sync(0xffffffffu, s, o);
        s2 += __shfl_xor_sync(0xffffffffu, s2, o);
    }
    int wid = k >> 5, lane = k & 31;
    if (lane == 0) { red[wid] = s; red[8 + wid] = s2; }
    __syncthreads();
    if (k < 32) {
        float a  = (k < 8) ? red[k]     : 0.f;
        float b2 = (k < 8) ? red[8 + k] : 0.f;
        #pragma unroll
        for (int o = 4; o > 0; o >>= 1) {
            a  += __shfl_xor_sync(0xffffffffu, a,  o);
            b2 += __shfl_xor_sync(0xffffffffu, b2, o);
        }
        if (k == 0) { red[0] = a; red[1] = b2; }
    }
    __syncthreads();
    float mu  = red[0] * (1.f / D);
    float var = red[1] * (1.f / D) - mu * mu;
    float r = rsqrtf(var + 1e-5f);
    out[(long)m * D + k] = (x - mu) * r * gamma[k] + beta[k];
}

// ---------------- launch ----------------------------------------------------
extern "C" void kernel_launch(void* const* d_in, const int* in_sizes, int n_in,
                              void* d_out, int out_size) {
    const float* tgt    = (const float*)d_in[0];
    const float* memory = (const float*)d_in[1];
    const float* qpos   = (const float*)d_in[2];
    const float* pos    = (const float*)d_in[3];
    const float* w_in   = (const float*)d_in[4];
    const float* b_in   = (const float*)d_in[5];
    const float* w_out  = (const float*)d_in[6];
    const float* b_out  = (const float*)d_in[7];
    const float* w_gate = (const float*)d_in[8];
    const float* b_gate = (const float*)d_in[9];
    const float* gamma  = (const float*)d_in[10];
    const float* beta   = (const float*)d_in[11];

    float *pQ, *pK, *pV, *pCtx, *pOut;
    __nv_bfloat16 *pAq, *pAk, *pAv, *pAc, *pWq, *pWk, *pWv, *pWo;
    cudaGetSymbolAddress((void**)&pQ,   g_Q);
    cudaGetSymbolAddress((void**)&pK,   g_K);
    cudaGetSymbolAddress((void**)&pV,   g_V);
    cudaGetSymbolAddress((void**)&pCtx, g_ctx);
    cudaGetSymbolAddress((void**)&pOut, g_out);
    cudaGetSymbolAddress((void**)&pAq,  g_Aq);
    cudaGetSymbolAddress((void**)&pAk,  g_Ak);
    cudaGetSymbolAddress((void**)&pAv,  g_Av);
    cudaGetSymbolAddress((void**)&pAc,  g_Ac);
    cudaGetSymbolAddress((void**)&pWq,  g_Wq);
    cudaGetSymbolAddress((void**)&pWk,  g_Wk);
    cudaGetSymbolAddress((void**)&pWv,  g_Wv);
    cudaGetSymbolAddress((void**)&pWo,  g_Wo);

    cudaFuncSetAttribute(gemm_mma, cudaFuncAttributeMaxDynamicSharedMemorySize, GEMM_SMEM);
    cudaFuncSetAttribute(attn_mma, cudaFuncAttributeMaxDynamicSharedMemorySize, ATT_SMEM);

    // operand conversions (hi/lo bf16 split)
    convert_act<<<(MQ*64 + 255)/256, 256>>>(tgt, qpos, pAq, MQ);
    convert_kv<<<(MK*64 + 255)/256, 256>>>(memory, pos, pAk, pAv);
    convert_w_all<<<(NEXP*64 + 255)/256, 256>>>(w_in, w_out, pWq, pWk, pWv, pWo);

    gate_kernel<<<(MQ*32 + 127)/128, 128>>>(tgt, w_gate, b_gate);

    // QKV projections on HMMA tensor cores
    gemm_mma<<<dim3(7, 10, 1), 512, GEMM_SMEM>>>(pAq, pWq, b_in, pQ, MQ, NEXP,
                                                 0, 0, 0, 0, 768, 0);
    gemm_mma<<<dim3(64, 10, 1), 512, GEMM_SMEM>>>(pAk, pWk, b_in, pK, MK, NEXP,
                                                  0, 0, 0, 0, 768, 256);
    gemm_mma<<<dim3(64, 10, 1), 512, GEMM_SMEM>>>(pAv, pWv, b_in, pV, MK, NEXP,
                                                  0, 0, 0, 0, 768, 512);

    // tensor-core flash attention
    attn_mma<<<dim3(NH, BB, NE), 128, ATT_SMEM>>>();

    // out projection (per expert via grid.z)
    convert_act<<<(NE*MQ*64 + 255)/256, 256>>>(pCtx, nullptr, pAc, NE*MQ);
    gemm_mma<<<dim3(7, 2, 5), 512, GEMM_SMEM>>>(pAc, pWo, b_out, pOut, MQ, D,
                                                (long)MQ*KA, (long)D*KCAT,
                                                D, (long)MQ*D, 0, 0);

    // gated combine + residual + LN
    combine_ln<<<MQ, 256>>>(tgt, gamma, beta, (float*)d_out);
}